// round 1
// baseline (speedup 1.0000x reference)
#include <cuda_runtime.h>
#include <math.h>

#define DIMC   96
#define NHEADS 3
#define HD     32
#define NTOK   49
#define PITCH  100
#define NTHR   192
// smem layout (floats): xs 64*100 | ws 96*100 | ks 49*100 | vs 49*100 | wb 96
#define SMEM_FLOATS 25896
#define SMEM_BYTES  (SMEM_FLOATS * 4)

__device__ float g_bias[NHEADS * NTOK * NTOK];

__global__ void bias_precompute(const float* __restrict__ rpb,
                                const int* __restrict__ rel) {
    int i = blockIdx.x * blockDim.x + threadIdx.x;
    if (i < NTOK * NTOK) {
        int idx = rel[i];
        #pragma unroll
        for (int h = 0; h < NHEADS; ++h)
            g_bias[h * (NTOK * NTOK) + i] = rpb[idx * NHEADS + h];
    }
}

__global__ void __launch_bounds__(NTHR, 2)
win_attn_kernel(const float* __restrict__ x,
                const float* __restrict__ mask,
                const float* __restrict__ qkv_w,
                const float* __restrict__ qkv_b,
                const float* __restrict__ proj_w,
                const float* __restrict__ proj_b,
                float* __restrict__ out) {
    extern __shared__ float sm[];
    float* xs = sm;          // 64 x PITCH : x tile, later attention output O
    float* ws = sm + 6400;   // 96 x PITCH : weight staging (qkv slices, proj)
    float* ks = sm + 16000;  // 49 x PITCH : k tile, later projected-out staging
    float* vs = sm + 20900;  // 49 x PITCH : v tile
    float* wb = sm + 25800;  // 96 : bias staging

    const int b   = blockIdx.x;
    const int wi  = b & 63;          // window index within image (BnW = img*64 + w)
    const int tid = threadIdx.x;
    const int n   = tid & 63;        // token row (49 valid, padded to 64)
    const int g   = tid >> 6;        // column group / head (0..2)
    const bool rowok = (n < NTOK);

    // ---- Phase 0: stage x tile (coalesced), zero pad rows ----
    const float* xg = x + (size_t)b * (NTOK * DIMC);
    for (int i = tid; i < NTOK * DIMC; i += NTHR)
        xs[(i / DIMC) * PITCH + (i % DIMC)] = xg[i];
    for (int i = tid; i < (64 - NTOK) * DIMC; i += NTHR)
        xs[(NTOK + i / DIMC) * PITCH + (i % DIMC)] = 0.0f;
    __syncthreads();

    // x row -> registers (pitch 100: conflict-free float4 reads across lanes)
    float xr[DIMC];
    {
        const float4* xrow = reinterpret_cast<const float4*>(xs + n * PITCH);
        #pragma unroll
        for (int j = 0; j < DIMC / 4; ++j) {
            float4 t = xrow[j];
            xr[4*j+0] = t.x; xr[4*j+1] = t.y; xr[4*j+2] = t.z; xr[4*j+3] = t.w;
        }
    }

    // ---- Phase 1a: Q slice (cols 0..95 of qkv) -> registers (head g of row n) ----
    float qreg[HD];
    {
        for (int i = tid; i < DIMC * DIMC; i += NTHR)
            ws[(i / DIMC) * PITCH + (i % DIMC)] = qkv_w[i];
        if (tid < DIMC) wb[tid] = qkv_b[tid];
        __syncthreads();
        const float scale = 0.17677669529663687f; // 32^-0.5
        #pragma unroll
        for (int cl = 0; cl < HD; ++cl) {
            const int c = g * HD + cl;
            const float4* wrow = reinterpret_cast<const float4*>(ws + c * PITCH);
            float acc = wb[c];
            #pragma unroll
            for (int j = 0; j < DIMC / 4; ++j) {
                float4 w4 = wrow[j];  // warp-uniform broadcast load
                acc += xr[4*j+0]*w4.x + xr[4*j+1]*w4.y
                     + xr[4*j+2]*w4.z + xr[4*j+3]*w4.w;
            }
            qreg[cl] = acc * scale;
        }
        __syncthreads();
    }

    // ---- Phase 1b: K and V slices -> smem ----
    for (int s = 1; s < 3; ++s) {
        const float* wg = qkv_w + s * DIMC * DIMC;
        for (int i = tid; i < DIMC * DIMC; i += NTHR)
            ws[(i / DIMC) * PITCH + (i % DIMC)] = wg[i];
        if (tid < DIMC) wb[tid] = qkv_b[s * DIMC + tid];
        __syncthreads();
        float* dst = (s == 1) ? ks : vs;
        for (int cl = 0; cl < HD; ++cl) {
            const int c = g * HD + cl;
            const float4* wrow = reinterpret_cast<const float4*>(ws + c * PITCH);
            float acc = wb[c];
            #pragma unroll
            for (int j = 0; j < DIMC / 4; ++j) {
                float4 w4 = wrow[j];
                acc += xr[4*j+0]*w4.x + xr[4*j+1]*w4.y
                     + xr[4*j+2]*w4.z + xr[4*j+3]*w4.w;
            }
            if (rowok) dst[n * PITCH + c] = acc;
        }
        __syncthreads();
    }

    // ---- Phase 2+3: logits, neg-softmax, A@V. Thread (h=g, n) owns one query row ----
    const int h = g;
    if (rowok) {
        float lg[NTOK];
        const float* brow = g_bias + h * (NTOK * NTOK) + n * NTOK;
        const float* mrow = mask + ((size_t)wi * NTOK + n) * NTOK;
        #pragma unroll
        for (int m = 0; m < NTOK; ++m) {
            const float4* krow = reinterpret_cast<const float4*>(ks + m * PITCH + h * HD);
            float acc = 0.0f;
            #pragma unroll
            for (int j = 0; j < HD / 4; ++j) {
                float4 k4 = krow[j];  // broadcast
                acc += qreg[4*j+0]*k4.x + qreg[4*j+1]*k4.y
                     + qreg[4*j+2]*k4.z + qreg[4*j+3]*k4.w;
            }
            lg[m] = acc + brow[m] + mrow[m];
        }
        // neg softmax: sign(l) * softmax(|l|), max-subtracted
        float M = 0.0f;
        #pragma unroll
        for (int m = 0; m < NTOK; ++m) M = fmaxf(M, fabsf(lg[m]));
        float ssum = 0.0f;
        #pragma unroll
        for (int m = 0; m < NTOK; ++m) {
            float l = lg[m];
            float e = __expf(fabsf(l) - M);
            ssum += e;
            lg[m] = (l > 0.0f) ? e : ((l < 0.0f) ? -e : 0.0f);
        }
        const float rinv = 1.0f / ssum;

        float oacc[HD];
        #pragma unroll
        for (int j = 0; j < HD; ++j) oacc[j] = 0.0f;
        #pragma unroll
        for (int m = 0; m < NTOK; ++m) {
            const float p = lg[m];
            const float4* vrow = reinterpret_cast<const float4*>(vs + m * PITCH + h * HD);
            #pragma unroll
            for (int j = 0; j < HD / 4; ++j) {
                float4 v4 = vrow[j];  // broadcast
                oacc[4*j+0] += p * v4.x; oacc[4*j+1] += p * v4.y;
                oacc[4*j+2] += p * v4.z; oacc[4*j+3] += p * v4.w;
            }
        }
        float4* orow = reinterpret_cast<float4*>(xs + n * PITCH + h * HD);
        #pragma unroll
        for (int j = 0; j < HD / 4; ++j) {
            float4 o4;
            o4.x = oacc[4*j+0] * rinv; o4.y = oacc[4*j+1] * rinv;
            o4.z = oacc[4*j+2] * rinv; o4.w = oacc[4*j+3] * rinv;
            orow[j] = o4;
        }
    }
    __syncthreads();

    // ---- Phase 4: projection. O rows are in xs (pad rows still zero). ----
    for (int i = tid; i < DIMC * DIMC; i += NTHR)
        ws[(i / DIMC) * PITCH + (i % DIMC)] = proj_w[i];
    if (tid < DIMC) wb[tid] = proj_b[tid];
    __syncthreads();

    float orr[DIMC];
    {
        const float4* xrow = reinterpret_cast<const float4*>(xs + n * PITCH);
        #pragma unroll
        for (int j = 0; j < DIMC / 4; ++j) {
            float4 t = xrow[j];
            orr[4*j+0] = t.x; orr[4*j+1] = t.y; orr[4*j+2] = t.z; orr[4*j+3] = t.w;
        }
    }
    for (int cl = 0; cl < HD; ++cl) {
        const int c = g * HD + cl;
        const float4* wrow = reinterpret_cast<const float4*>(ws + c * PITCH);
        float acc = wb[c];
        #pragma unroll
        for (int j = 0; j < DIMC / 4; ++j) {
            float4 w4 = wrow[j];
            acc += orr[4*j+0]*w4.x + orr[4*j+1]*w4.y
                 + orr[4*j+2]*w4.z + orr[4*j+3]*w4.w;
        }
        if (rowok) ks[n * PITCH + c] = acc;
    }
    __syncthreads();

    // ---- Phase 5: coalesced store ----
    float* og = out + (size_t)b * (NTOK * DIMC);
    for (int i = tid; i < NTOK * DIMC; i += NTHR)
        og[i] = ks[(i / DIMC) * PITCH + (i % DIMC)];
}

extern "C" void kernel_launch(void* const* d_in, const int* in_sizes, int n_in,
                              void* d_out, int out_size) {
    const float* x      = (const float*)d_in[0];
    const float* mask   = (const float*)d_in[1];
    const float* qkv_w  = (const float*)d_in[2];
    const float* qkv_b  = (const float*)d_in[3];
    const float* proj_w = (const float*)d_in[4];
    const float* proj_b = (const float*)d_in[5];
    const float* rpb    = (const float*)d_in[6];
    const int*   rel    = (const int*)d_in[7];
    float* out = (float*)d_out;

    cudaFuncSetAttribute(win_attn_kernel,
                         cudaFuncAttributeMaxDynamicSharedMemorySize, SMEM_BYTES);

    bias_precompute<<<(NTOK * NTOK + 127) / 128, 128>>>(rpb, rel);
    win_attn_kernel<<<4096, NTHR, SMEM_BYTES>>>(x, mask, qkv_w, qkv_b,
                                                proj_w, proj_b, out);
}

// round 2
// speedup vs baseline: 1.2247x; 1.2247x over previous
#include <cuda_runtime.h>
#include <math.h>

#define DIMC   96
#define NHEADS 3
#define HD     32
#define NTOK   49
#define PITCH  100
#define NTHR   192
// smem layout (floats): xs 64*100 | ws 96*100 | ks 49*100 | vs 49*100 | wb 96
#define SMEM_FLOATS 25896
#define SMEM_BYTES  (SMEM_FLOATS * 4)

typedef unsigned long long u64;

// packed fp32x2 FMA: d = a*b + d (elementwise on 2 packed floats)
__device__ __forceinline__ void fma2(u64& d, u64 a, u64 b) {
    asm("fma.rn.f32x2 %0, %1, %2, %0;" : "+l"(d) : "l"(a), "l"(b));
}
__device__ __forceinline__ u64 add2(u64 a, u64 b) {
    u64 d; asm("add.rn.f32x2 %0, %1, %2;" : "=l"(d) : "l"(a), "l"(b)); return d;
}
__device__ __forceinline__ float hsum2(u64 v) {
    float lo, hi; asm("mov.b64 {%0, %1}, %2;" : "=f"(lo), "=f"(hi) : "l"(v));
    return lo + hi;
}
__device__ __forceinline__ u64 dup2(float x) {
    u64 r; asm("mov.b64 %0, {%1, %1};" : "=l"(r) : "f"(x)); return r;
}
__device__ __forceinline__ void upk2(u64 v, float& lo, float& hi) {
    asm("mov.b64 {%0, %1}, %2;" : "=f"(lo), "=f"(hi) : "l"(v));
}

__device__ float g_bias[NHEADS * NTOK * NTOK];

__global__ void bias_precompute(const float* __restrict__ rpb,
                                const int* __restrict__ rel) {
    int i = blockIdx.x * blockDim.x + threadIdx.x;
    if (i < NTOK * NTOK) {
        int idx = rel[i];
        #pragma unroll
        for (int h = 0; h < NHEADS; ++h)
            g_bias[h * (NTOK * NTOK) + i] = rpb[idx * NHEADS + h];
    }
}

// 96-deep dot product: xr2[24 pairs... 48 u64] . w-row (smem), 4 indep chains
__device__ __forceinline__ float dot96(const u64* __restrict__ xr2,
                                       const float* __restrict__ wrow_f) {
    const ulonglong2* wrow = reinterpret_cast<const ulonglong2*>(wrow_f);
    u64 a0 = 0, a1 = 0, a2 = 0, a3 = 0;
    #pragma unroll
    for (int j = 0; j < 24; j += 2) {
        ulonglong2 w2 = wrow[j];        // 16B LDS (broadcast within warp)
        fma2(a0, xr2[2*j],     w2.x);
        fma2(a1, xr2[2*j + 1], w2.y);
        ulonglong2 w3 = wrow[j + 1];
        fma2(a2, xr2[2*j + 2], w3.x);
        fma2(a3, xr2[2*j + 3], w3.y);
    }
    return hsum2(add2(add2(a0, a1), add2(a2, a3)));
}

__global__ void __launch_bounds__(NTHR, 2)
win_attn_kernel(const float* __restrict__ x,
                const float* __restrict__ mask,
                const float* __restrict__ qkv_w,
                const float* __restrict__ qkv_b,
                const float* __restrict__ proj_w,
                const float* __restrict__ proj_b,
                float* __restrict__ out) {
    extern __shared__ float sm[];
    float* xs = sm;          // 64 x PITCH : x tile, later attention output O
    float* ws = sm + 6400;   // 96 x PITCH : weight staging
    float* ks = sm + 16000;  // 49 x PITCH : k tile, later output staging
    float* vs = sm + 20900;  // 49 x PITCH : v tile
    float* wb = sm + 25800;  // 96 : bias staging

    const int b   = blockIdx.x;
    const int wi  = b & 63;
    const int tid = threadIdx.x;
    const int n   = tid & 63;        // token row (49 valid, padded to 64)
    const int g   = tid >> 6;        // column group / head (0..2)
    const bool rowok = (n < NTOK);

    // ---- Phase 0: stage x tile (coalesced), zero pad rows ----
    const float* xg = x + (size_t)b * (NTOK * DIMC);
    for (int i = tid; i < NTOK * DIMC; i += NTHR)
        xs[(i / DIMC) * PITCH + (i % DIMC)] = xg[i];
    for (int i = tid; i < (64 - NTOK) * DIMC; i += NTHR)
        xs[(NTOK + i / DIMC) * PITCH + (i % DIMC)] = 0.0f;
    __syncthreads();

    // x row -> packed registers (48 u64 = 96 floats)
    u64 xr2[48];
    {
        const ulonglong2* xrow = reinterpret_cast<const ulonglong2*>(xs + n * PITCH);
        #pragma unroll
        for (int j = 0; j < 24; ++j) {
            ulonglong2 t = xrow[j];
            xr2[2*j] = t.x; xr2[2*j + 1] = t.y;
        }
    }

    // ---- Phase 1a: Q slice -> packed registers (head g of row n) ----
    u64 q2[16];   // 32 floats, pre-scaled
    {
        for (int i = tid; i < DIMC * DIMC; i += NTHR)
            ws[(i / DIMC) * PITCH + (i % DIMC)] = qkv_w[i];
        if (tid < DIMC) wb[tid] = qkv_b[tid];
        __syncthreads();
        const float scale = 0.17677669529663687f; // 32^-0.5
        #pragma unroll 2
        for (int cl = 0; cl < HD; cl += 2) {
            const int c = g * HD + cl;
            float v0 = (dot96(xr2, ws + c * PITCH) + wb[c]) * scale;
            float v1 = (dot96(xr2, ws + (c + 1) * PITCH) + wb[c + 1]) * scale;
            asm("mov.b64 %0, {%1, %2};" : "=l"(q2[cl >> 1]) : "f"(v0), "f"(v1));
        }
        __syncthreads();
    }

    // ---- Phase 1b: K and V slices -> smem ----
    for (int s = 1; s < 3; ++s) {
        const float* wg = qkv_w + s * DIMC * DIMC;
        for (int i = tid; i < DIMC * DIMC; i += NTHR)
            ws[(i / DIMC) * PITCH + (i % DIMC)] = wg[i];
        if (tid < DIMC) wb[tid] = qkv_b[s * DIMC + tid];
        __syncthreads();
        float* dst = (s == 1) ? ks : vs;
        #pragma unroll 2
        for (int cl = 0; cl < HD; ++cl) {
            const int c = g * HD + cl;
            float acc = dot96(xr2, ws + c * PITCH) + wb[c];
            if (rowok) dst[n * PITCH + c] = acc;
        }
        __syncthreads();
    }

    // ---- Phase 2+3: logits, neg-softmax, A@V ----
    const int h = g;
    if (rowok) {
        float lg[NTOK];
        const float* brow = g_bias + h * (NTOK * NTOK) + n * NTOK;
        const float* mrow = mask + ((size_t)wi * NTOK + n) * NTOK;
        #pragma unroll 7
        for (int m = 0; m < NTOK; ++m) {
            const ulonglong2* krow =
                reinterpret_cast<const ulonglong2*>(ks + m * PITCH + h * HD);
            u64 a0 = 0, a1 = 0, a2 = 0, a3 = 0;
            #pragma unroll
            for (int j = 0; j < 8; j += 2) {
                ulonglong2 k2 = krow[j];
                fma2(a0, q2[2*j],     k2.x);
                fma2(a1, q2[2*j + 1], k2.y);
                ulonglong2 k3 = krow[j + 1];
                fma2(a2, q2[2*j + 2], k3.x);
                fma2(a3, q2[2*j + 3], k3.y);
            }
            lg[m] = hsum2(add2(add2(a0, a1), add2(a2, a3))) + brow[m] + mrow[m];
        }
        // neg softmax: sign(l) * softmax(|l|), max-subtracted
        float M = 0.0f;
        #pragma unroll
        for (int m = 0; m < NTOK; ++m) M = fmaxf(M, fabsf(lg[m]));
        float ssum = 0.0f;
        #pragma unroll
        for (int m = 0; m < NTOK; ++m) {
            float l = lg[m];
            float e = __expf(fabsf(l) - M);
            ssum += e;
            lg[m] = (l > 0.0f) ? e : ((l < 0.0f) ? -e : 0.0f);
        }
        const float rinv = 1.0f / ssum;

        u64 oacc[16];   // 32 floats packed
        #pragma unroll
        for (int j = 0; j < 16; ++j) oacc[j] = 0;
        #pragma unroll 7
        for (int m = 0; m < NTOK; ++m) {
            const u64 p2 = dup2(lg[m]);
            const ulonglong2* vrow =
                reinterpret_cast<const ulonglong2*>(vs + m * PITCH + h * HD);
            #pragma unroll
            for (int j = 0; j < 8; ++j) {
                ulonglong2 v2 = vrow[j];
                fma2(oacc[2*j],     p2, v2.x);
                fma2(oacc[2*j + 1], p2, v2.y);
            }
        }
        float2* orow = reinterpret_cast<float2*>(xs + n * PITCH + h * HD);
        #pragma unroll
        for (int j = 0; j < 16; ++j) {
            float lo, hi; upk2(oacc[j], lo, hi);
            float2 o2; o2.x = lo * rinv; o2.y = hi * rinv;
            orow[j] = o2;
        }
    }
    __syncthreads();

    // ---- Phase 4: projection. O rows are in xs (pad rows still zero). ----
    for (int i = tid; i < DIMC * DIMC; i += NTHR)
        ws[(i / DIMC) * PITCH + (i % DIMC)] = proj_w[i];
    if (tid < DIMC) wb[tid] = proj_b[tid];
    __syncthreads();

    // reload O row packed
    u64 or2[48];
    {
        const ulonglong2* xrow = reinterpret_cast<const ulonglong2*>(xs + n * PITCH);
        #pragma unroll
        for (int j = 0; j < 24; ++j) {
            ulonglong2 t = xrow[j];
            or2[2*j] = t.x; or2[2*j + 1] = t.y;
        }
    }
    #pragma unroll 2
    for (int cl = 0; cl < HD; ++cl) {
        const int c = g * HD + cl;
        float acc = dot96(or2, ws + c * PITCH) + wb[c];
        if (rowok) ks[n * PITCH + c] = acc;
    }
    __syncthreads();

    // ---- Phase 5: coalesced store ----
    float* og = out + (size_t)b * (NTOK * DIMC);
    for (int i = tid; i < NTOK * DIMC; i += NTHR)
        og[i] = ks[(i / DIMC) * PITCH + (i % DIMC)];
}

extern "C" void kernel_launch(void* const* d_in, const int* in_sizes, int n_in,
                              void* d_out, int out_size) {
    const float* x      = (const float*)d_in[0];
    const float* mask   = (const float*)d_in[1];
    const float* qkv_w  = (const float*)d_in[2];
    const float* qkv_b  = (const float*)d_in[3];
    const float* proj_w = (const float*)d_in[4];
    const float* proj_b = (const float*)d_in[5];
    const float* rpb    = (const float*)d_in[6];
    const int*   rel    = (const int*)d_in[7];
    float* out = (float*)d_out;

    cudaFuncSetAttribute(win_attn_kernel,
                         cudaFuncAttributeMaxDynamicSharedMemorySize, SMEM_BYTES);

    bias_precompute<<<(NTOK * NTOK + 127) / 128, 128>>>(rpb, rel);
    win_attn_kernel<<<4096, NTHR, SMEM_BYTES>>>(x, mask, qkv_w, qkv_b,
                                                proj_w, proj_b, out);
}